// round 14
// baseline (speedup 1.0000x reference)
#include <cuda_runtime.h>

#define IMG_W 1280
#define IMG_H 1024
#define IMG_B 8
#define N_CH  3

#define PLANE   (IMG_H * IMG_W)          // 1,310,720
#define YGRPS   (IMG_H / 4)              // 256 groups of 4 ADJACENT rows
#define NTHREADS_TOTAL (IMG_B * YGRPS * IMG_W)   // 2,621,440
#define BLOCK   128

__device__ __forceinline__ float rcp_approx(float x) {
    float r;
    asm("rcp.approx.f32 %0, %1;" : "=f"(r) : "f"(x));
    return r;
}

__global__ __launch_bounds__(BLOCK) void synth_view_kernel(
    const float* __restrict__ img,   // [B,3,H,W]
    const float* __restrict__ disp,  // [B,1,H,W]
    const float* __restrict__ sK,    // [B,4,4]
    const float* __restrict__ tK,    // [B,4,4]
    const float* __restrict__ tv,    // [B,3]
    float* __restrict__ out)         // [B,3,H,W]
{
    int t = blockIdx.x * BLOCK + threadIdx.x;   // grid divides exactly

    // t -> (b, yg, x): lanes consecutive in x; thread owns 4 ADJACENT rows
    int b   = t / (YGRPS * IMG_W);
    int rem = t - b * (YGRPS * IMG_W);
    int yg  = rem / IMG_W;               // 0..255
    int x   = rem - yg * IMG_W;
    int y0r = yg * 4;                    // first of 4 adjacent rows

    // ---- per-batch folded camera coefficients (once per thread) ----
    const float* sk = sK + b * 16;
    const float* tk = tK + b * 16;
    float fxs = __ldg(sk + 0), cxs = __ldg(sk + 2);
    float fys = __ldg(sk + 5), cys = __ldg(sk + 6);
    float fxt = __ldg(tk + 0), cxt = __ldg(tk + 2);
    float fyt = __ldg(tk + 5), cyt = __ldg(tk + 6);
    float tx = __ldg(tv + b * 3 + 0);
    float ty = __ldg(tv + b * 3 + 1);
    float tz = __ldg(tv + b * 3 + 2);

    float ia  = rcp_approx(fxs);
    float ie  = rcp_approx(fys);
    float Ax  = fxt * ia;
    float Bx  = fmaf(-fxt * cxs, ia, cxt);
    float Cx  = fmaf(fxt, tx, cxt * tz);
    float Ay  = fyt * ie;
    float By  = fmaf(-fyt * cys, ie, cyt);
    float Cy  = fmaf(fyt, ty, cyt * tz);

    const float MIN_DISP = 1.0f / 255.0f;
    const float MAX_DISP = 1.0f / 10.0f;
    const float DRANGE   = MAX_DISP - MIN_DISP;
    const float SXW = (float)IMG_W / (float)(IMG_W - 1);
    const float SYH = (float)IMG_H / (float)(IMG_H - 1);
    const float TZE = tz + 1e-7f;        // z-offset + eps, folded

    float ux = fmaf(Ax, (float)x, Bx);   // x-part, shared by all 4 rows

    int disp_base = b * PLANE + y0r * IMG_W + x;   // row k at + k*IMG_W
    int img_base  = b * (N_CH * PLANE);

    // batch the 4 disp loads (coalesced per row)
    float dv[4];
#pragma unroll
    for (int k = 0; k < 4; k++)
        dv[k] = __ldcs(disp + disp_base + k * IMG_W);

    int   i0[4];
    float wxv[4], wyv[4];

    float vy = fmaf(Ay, (float)y0r, By);     // incremental y coefficient

#pragma unroll
    for (int k = 0; k < 4; k++) {
        float sd = fmaf(DRANGE, dv[k], MIN_DISP);

        // projection as a single ratio (depth cancels):
        //   u/(z+eps) = (ux + Cx*sd) / (1 + (tz+eps)*sd)
        float r  = rcp_approx(fmaf(TZE, sd, 1.0f));   // shared denominator
        float xs = fmaf(fmaf(Cx, sd, ux) * r, SXW, -0.5f);
        float ys = fmaf(fmaf(Cy, sd, vy) * r, SYH, -0.5f);

        // border clamp folded into weights: base in [0,W-2]x[0,H-2], w in [0,1]
        // (exactly matches clamp-index/unclamped-weight reference semantics)
        float x0cf = fminf(fmaxf(floorf(xs), 0.0f), (float)(IMG_W - 2));
        float y0cf = fminf(fmaxf(floorf(ys), 0.0f), (float)(IMG_H - 2));
        wxv[k] = fminf(fmaxf(xs - x0cf, 0.0f), 1.0f);
        wyv[k] = fminf(fmaxf(ys - y0cf, 0.0f), 1.0f);

        i0[k] = (int)y0cf * IMG_W + (int)x0cf;

        vy += Ay;
    }

    int out_base = img_base + y0r * IMG_W + x;

#pragma unroll
    for (int ch = 0; ch < N_CH; ch++) {
        const float* im = img + img_base + ch * PLANE;
        float res[4];
#pragma unroll
        for (int k = 0; k < 4; k++) {
            const float* p = im + i0[k];
            float v00 = __ldg(p);
            float v01 = __ldg(p + 1);
            float v10 = __ldg(p + IMG_W);
            float v11 = __ldg(p + IMG_W + 1);
            float wx = wxv[k], wy = wyv[k];
            float top = fmaf(v01 - v00, wx, v00);
            float bot = fmaf(v11 - v10, wx, v10);
            res[k] = fmaf(bot - top, wy, top);
        }
#pragma unroll
        for (int k = 0; k < 4; k++)
            __stcs(out + out_base + ch * PLANE + k * IMG_W, res[k]);  // coalesced
    }
}

extern "C" void kernel_launch(void* const* d_in, const int* in_sizes, int n_in,
                              void* d_out, int out_size) {
    const float* img  = (const float*)d_in[0];
    const float* disp = (const float*)d_in[1];
    const float* sK   = (const float*)d_in[2];
    const float* tK   = (const float*)d_in[3];
    const float* tv   = (const float*)d_in[4];
    float* out = (float*)d_out;

    int grid = NTHREADS_TOTAL / BLOCK;   // 20,480 blocks, exact
    synth_view_kernel<<<grid, BLOCK>>>(img, disp, sK, tK, tv, out);
}

// round 15
// speedup vs baseline: 1.1288x; 1.1288x over previous
#include <cuda_runtime.h>

#define IMG_W 1280
#define IMG_H 1024
#define IMG_B 8
#define N_CH  3

#define PLANE   (IMG_H * IMG_W)          // 1,310,720
#define YGRPS   (IMG_H / 4)              // 256 groups of 4 ADJACENT rows
#define NTHREADS_TOTAL (IMG_B * YGRPS * IMG_W)   // 2,621,440
#define BLOCK   128

__global__ __launch_bounds__(BLOCK) void synth_view_kernel(
    const float* __restrict__ img,   // [B,3,H,W]
    const float* __restrict__ disp,  // [B,1,H,W]
    const float* __restrict__ sK,    // [B,4,4]
    const float* __restrict__ tK,    // [B,4,4]
    const float* __restrict__ tv,    // [B,3]
    float* __restrict__ out)         // [B,3,H,W]
{
    int t = blockIdx.x * BLOCK + threadIdx.x;   // grid divides exactly

    // t -> (b, yg, x): lanes consecutive in x; thread owns 4 ADJACENT rows
    int b   = t / (YGRPS * IMG_W);
    int rem = t - b * (YGRPS * IMG_W);
    int yg  = rem / IMG_W;               // 0..255
    int x   = rem - yg * IMG_W;
    int y0r = yg * 4;                    // first of 4 adjacent rows

    // ---- per-batch folded camera coefficients (once per thread) ----
    const float* sk = sK + b * 16;
    const float* tk = tK + b * 16;
    float fxs = __ldg(sk + 0), cxs = __ldg(sk + 2);
    float fys = __ldg(sk + 5), cys = __ldg(sk + 6);
    float fxt = __ldg(tk + 0), cxt = __ldg(tk + 2);
    float fyt = __ldg(tk + 5), cyt = __ldg(tk + 6);
    float tx = __ldg(tv + b * 3 + 0);
    float ty = __ldg(tv + b * 3 + 1);
    float tz = __ldg(tv + b * 3 + 2);

    float ia  = __frcp_rn(fxs);
    float ie  = __frcp_rn(fys);
    float Ax  = fxt * ia;
    float Bx  = fmaf(-fxt * cxs, ia, cxt);
    float Cx  = fmaf(fxt, tx, cxt * tz);
    float Ay  = fyt * ie;
    float By  = fmaf(-fyt * cys, ie, cyt);
    float Cy  = fmaf(fyt, ty, cyt * tz);

    const float MIN_DISP = 1.0f / 255.0f;
    const float MAX_DISP = 1.0f / 10.0f;
    const float DRANGE   = MAX_DISP - MIN_DISP;
    const float SXW = (float)IMG_W / (float)(IMG_W - 1);
    const float SYH = (float)IMG_H / (float)(IMG_H - 1);
    const float TZE = tz + 1e-7f;        // z-offset + eps, folded

    float ux = fmaf(Ax, (float)x, Bx);   // x-part, shared by all 4 rows

    int disp_base = b * PLANE + y0r * IMG_W + x;   // row k at + k*IMG_W
    int img_base  = b * (N_CH * PLANE);

    // batch the 4 disp loads (coalesced per row)
    float dv[4];
#pragma unroll
    for (int k = 0; k < 4; k++)
        dv[k] = __ldcs(disp + disp_base + k * IMG_W);

    int   i0[4];
    float wxv[4], wyv[4];

    float vy = fmaf(Ay, (float)y0r, By);     // incremental y coefficient

#pragma unroll
    for (int k = 0; k < 4; k++) {
        float sd = fmaf(DRANGE, dv[k], MIN_DISP);

        // projection as a single ratio (depth cancels):
        //   u/(z+eps) = (ux + Cx*sd) / (1 + (tz+eps)*sd)
        float r  = __frcp_rn(fmaf(TZE, sd, 1.0f));   // one rcp chain, no asm
        float xs = fmaf(fmaf(Cx, sd, ux) * r, SXW, -0.5f);
        float ys = fmaf(fmaf(Cy, sd, vy) * r, SYH, -0.5f);

        // border clamp folded into weights: base in [0,W-2]x[0,H-2], w in [0,1]
        // (exactly matches clamp-index/unclamped-weight reference semantics)
        float x0cf = fminf(fmaxf(floorf(xs), 0.0f), (float)(IMG_W - 2));
        float y0cf = fminf(fmaxf(floorf(ys), 0.0f), (float)(IMG_H - 2));
        wxv[k] = fminf(fmaxf(xs - x0cf, 0.0f), 1.0f);
        wyv[k] = fminf(fmaxf(ys - y0cf, 0.0f), 1.0f);

        i0[k] = (int)y0cf * IMG_W + (int)x0cf;

        vy += Ay;
    }

    int out_base = img_base + y0r * IMG_W + x;

#pragma unroll
    for (int ch = 0; ch < N_CH; ch++) {
        const float* im = img + img_base + ch * PLANE;
        float res[4];
#pragma unroll
        for (int k = 0; k < 4; k++) {
            const float* p = im + i0[k];
            float v00 = __ldg(p);
            float v01 = __ldg(p + 1);
            float v10 = __ldg(p + IMG_W);
            float v11 = __ldg(p + IMG_W + 1);
            float wx = wxv[k], wy = wyv[k];
            float top = fmaf(v01 - v00, wx, v00);
            float bot = fmaf(v11 - v10, wx, v10);
            res[k] = fmaf(bot - top, wy, top);
        }
#pragma unroll
        for (int k = 0; k < 4; k++)
            __stcs(out + out_base + ch * PLANE + k * IMG_W, res[k]);  // coalesced
    }
}

extern "C" void kernel_launch(void* const* d_in, const int* in_sizes, int n_in,
                              void* d_out, int out_size) {
    const float* img  = (const float*)d_in[0];
    const float* disp = (const float*)d_in[1];
    const float* sK   = (const float*)d_in[2];
    const float* tK   = (const float*)d_in[3];
    const float* tv   = (const float*)d_in[4];
    float* out = (float*)d_out;

    int grid = NTHREADS_TOTAL / BLOCK;   // 20,480 blocks, exact
    synth_view_kernel<<<grid, BLOCK>>>(img, disp, sK, tK, tv, out);
}